// round 10
// baseline (speedup 1.0000x reference)
#include <cuda_runtime.h>

#define Bn    2
#define CHn   256
#define Hn    512
#define Wn    512
#define HW    (Hn*Wn)            // 262144
#define NPIX  (Bn*HW)            // 524288
#define NITER 5
#define NBH   128                // blocks per batch
#define NB    (Bn*NBH)           // 256
#define NT    256                // threads/block
#define WPT   2                  // words (4px) per thread -> block covers 512 words = 4 rows
#define TAG   1

// -------- persistent scratch (overwrite-only; zero-init at module load) --------
struct __align__(128) Slot { int4 v; int4 pad[7]; };
__device__ Slot     g_mm[NB];               // per-block minmax (flipped bits, tag in .w)
__device__ Slot     g_tt[NB];               // per-block totals (tag<<20 in .w)
__device__ Slot     g_st[NITER][NB];        // per-block fg stats per iter ((tag<<20)|cnt in .w)
__device__ unsigned g_alf[NITER][NPIX/4];   // per-iteration alpha words (boundary rows used)

__device__ __forceinline__ unsigned fflip(float f) {
    unsigned u = __float_as_uint(f);
    return (u & 0x80000000u) ? ~u : (u | 0x80000000u);
}
__device__ __forceinline__ float funflip(unsigned u) {
    return (u & 0x80000000u) ? __uint_as_float(u & 0x7FFFFFFFu) : __uint_as_float(~u);
}
__device__ __forceinline__ void st_rel_i4(int4* p, int4 v) {
    asm volatile("st.release.gpu.global.v4.u32 [%0], {%1,%2,%3,%4};"
                 :: "l"(p), "r"(v.x), "r"(v.y), "r"(v.z), "r"(v.w) : "memory");
}
__device__ __forceinline__ int4 ld_acq_i4(const int4* p) {
    int4 v;
    asm volatile("ld.acquire.gpu.global.v4.u32 {%0,%1,%2,%3}, [%4];"
                 : "=r"(v.x), "=r"(v.y), "=r"(v.z), "=r"(v.w) : "l"(p) : "memory");
    return v;
}

// exact-floor quantization: fast reciprocal path, correctly-rounded-div fallback
__device__ __forceinline__ int qz(float v, float mn, float denom, float r255) {
    float t  = __fsub_rn(v, mn);
    float e  = __fmul_rn(t, r255);
    float fl = floorf(e);
    float fr = __fsub_rn(e, fl);
    if (fabsf(__fsub_rn(fr, 0.5f)) > 0.499f) {
        fl = floorf(__fmul_rn(__fdiv_rn(t, denom), 255.0f));
    }
    return (int)fminf(fmaxf(fl, 0.0f), 255.0f);
}

// ============================================================
__global__ void __launch_bounds__(NT, 2)
k_main(const float* __restrict__ feat, const int* __restrict__ mask,
       float* __restrict__ out) {
    const int tid  = threadIdx.x;
    const int wid  = tid >> 5, lane = tid & 31;
    const int WB   = blockIdx.x * (NT * WPT);      // block word base
    const int bb   = blockIdx.x >> 7;              // batch
    const int abase = bb * NBH;

    __shared__ unsigned salpha[NT * WPT];          // 512 words = 4 rows
    __shared__ int      sred[8][8];
    __shared__ int      spp[4][8];
    __shared__ float    smF[3], smB[3], sMM[2];
    __shared__ int      sT[3];

    int lw[WPT], idx4[WPT], yv[WPT], cv[WPT], lrv[WPT];
    const float* fb[WPT];
#pragma unroll
    for (int u = 0; u < WPT; u++) {
        lw[u]   = tid + u * NT;
        idx4[u] = WB + lw[u];
        yv[u]   = (idx4[u] >> 7) & (Hn - 1);
        cv[u]   = lw[u] & 127;
        lrv[u]  = lw[u] >> 7;                      // 0..3
        fb[u]   = feat + (size_t)bb * CHn * HW + ((idx4[u] & 0xFFFF) << 2);
    }

    // ---------- phase 1: per-batch min/max (features kept in registers) ----------
    float4 C0[WPT], C1[WPT], C2[WPT]; int4 MK[WPT];
    {
        float lmn = __int_as_float(0x7F7FFFFF), lmx = -lmn;
#pragma unroll
        for (int u = 0; u < WPT; u++) {
            C0[u] = *(const float4*)(fb[u]);
            C1[u] = *(const float4*)(fb[u] + HW);
            C2[u] = *(const float4*)(fb[u] + 2 * HW);
            MK[u] = ((const int4*)mask)[idx4[u]];
            lmn = fminf(lmn, fminf(fminf(fminf(C0[u].x, C0[u].y), fminf(C0[u].z, C0[u].w)),
                        fminf(fminf(fminf(C1[u].x, C1[u].y), fminf(C1[u].z, C1[u].w)),
                              fminf(fminf(C2[u].x, C2[u].y), fminf(C2[u].z, C2[u].w)))));
            lmx = fmaxf(lmx, fmaxf(fmaxf(fmaxf(C0[u].x, C0[u].y), fmaxf(C0[u].z, C0[u].w)),
                        fmaxf(fmaxf(fmaxf(C1[u].x, C1[u].y), fmaxf(C1[u].z, C1[u].w)),
                              fmaxf(fmaxf(C2[u].x, C2[u].y), fmaxf(C2[u].z, C2[u].w)))));
        }
        unsigned lmin = __reduce_min_sync(0xFFFFFFFFu, fflip(lmn));
        unsigned lmax = __reduce_max_sync(0xFFFFFFFFu, fflip(lmx));
        if (lane == 0) { sred[wid][0] = (int)lmin; sred[wid][1] = (int)lmax; }
        __syncthreads();
        if (wid == 0) {
            unsigned a = (lane < 8) ? (unsigned)sred[lane][0] : 0xFFFFFFFFu;
            unsigned b = (lane < 8) ? (unsigned)sred[lane][1] : 0u;
            a = min(a, __shfl_xor_sync(0xFFFFFFFFu, a, 1));
            b = max(b, __shfl_xor_sync(0xFFFFFFFFu, b, 1));
            a = min(a, __shfl_xor_sync(0xFFFFFFFFu, a, 2));
            b = max(b, __shfl_xor_sync(0xFFFFFFFFu, b, 2));
            a = min(a, __shfl_xor_sync(0xFFFFFFFFu, a, 4));
            b = max(b, __shfl_xor_sync(0xFFFFFFFFu, b, 4));
            if (lane == 0)
                st_rel_i4(&g_mm[blockIdx.x].v, make_int4((int)a, (int)b, 0, TAG));
        }
        if (tid < 128) {
            const int4* sp = &g_mm[abase + tid].v;
            int4 p;
            do { p = ld_acq_i4(sp); } while (p.w != TAG);
            unsigned mnl = __reduce_min_sync(0xFFFFFFFFu, (unsigned)p.x);
            unsigned mxl = __reduce_max_sync(0xFFFFFFFFu, (unsigned)p.y);
            if (lane == 0) { spp[wid][0] = (int)mnl; spp[wid][1] = (int)mxl; }
        }
        __syncthreads();
        if (wid == 0) {
            unsigned a = (lane < 4) ? (unsigned)spp[lane][0] : 0xFFFFFFFFu;
            unsigned b = (lane < 4) ? (unsigned)spp[lane][1] : 0u;
            a = min(a, __shfl_xor_sync(0xFFFFFFFFu, a, 1));
            b = max(b, __shfl_xor_sync(0xFFFFFFFFu, b, 1));
            a = min(a, __shfl_xor_sync(0xFFFFFFFFu, a, 2));
            b = max(b, __shfl_xor_sync(0xFFFFFFFFu, b, 2));
            if (lane == 0) { sMM[0] = funflip(a); sMM[1] = funflip(b); }
        }
        __syncthreads();
    }

    // ---------- phase 2: quantize + trimap + alpha0 + stats ----------
    unsigned rw[WPT], gw[WPT], bw[WPT], fixm[WPT], fixv[WPT], aw[WPT];
    {
        float mn = sMM[0], mx = sMM[1];
        float denom = __fadd_rn(__fsub_rn(mx, mn), 1e-12f);
        float r255  = __fmul_rn(__frcp_rn(denom), 255.0f);

#pragma unroll
        for (int u = 0; u < WPT; u++) {
            float rr[4] = {C0[u].x, C0[u].y, C0[u].z, C0[u].w};
            float gg[4] = {C1[u].x, C1[u].y, C1[u].z, C1[u].w};
            float bl[4] = {C2[u].x, C2[u].y, C2[u].z, C2[u].w};
            int   mm[4] = {MK[u].x, MK[u].y, MK[u].z, MK[u].w};
            const int y = yv[u];
            const int x = (idx4[u] & 127) << 2;
            rw[u] = gw[u] = bw[u] = fixm[u] = fixv[u] = aw[u] = 0;
            const bool yc = (y >= 230) && (y < 281);
            const bool yb = (y < 51) || (y >= 461);
#pragma unroll
            for (int j = 0; j < 4; j++) {
                unsigned q0 = (unsigned)qz(rr[j], mn, denom, r255);
                unsigned q1 = (unsigned)qz(gg[j], mn, denom, r255);
                unsigned q2 = (unsigned)qz(bl[j], mn, denom, r255);
                int xj = x + j;
                bool center = yc && (xj >= 230) && (xj < 281);
                bool border = yb || (xj < 51) || (xj >= 461);
                int tri = center ? 1 : (border ? 0 : (mm[j] == 1 ? 3 : 2));
                rw[u] |= q0 << (8 * j);
                gw[u] |= q1 << (8 * j);
                bw[u] |= q2 << (8 * j);
                if (tri <= 1) {
                    fixm[u] |= 255u << (8 * j);
                    if (tri == 1) fixv[u] |= 1u << (8 * j);
                }
                if (tri == 1 || tri == 3) aw[u] |= 1u << (8 * j);
            }
            if (lrv[u] == 0 || lrv[u] == 3)
                __stcg(&g_alf[0][idx4[u]], aw[u]);
            salpha[lw[u]] = aw[u];
        }

        int s[7];
        s[0] = (int)__dp4a(rw[1], aw[1], __dp4a(rw[0], aw[0], 0u));
        s[1] = (int)__dp4a(gw[1], aw[1], __dp4a(gw[0], aw[0], 0u));
        s[2] = (int)__dp4a(bw[1], aw[1], __dp4a(bw[0], aw[0], 0u));
        s[3] = (int)__dp4a(0x01010101u, aw[1], __dp4a(0x01010101u, aw[0], 0u));
        s[4] = (int)__dp4a(rw[1], 0x01010101u, __dp4a(rw[0], 0x01010101u, 0u));
        s[5] = (int)__dp4a(gw[1], 0x01010101u, __dp4a(gw[0], 0x01010101u, 0u));
        s[6] = (int)__dp4a(bw[1], 0x01010101u, __dp4a(bw[0], 0x01010101u, 0u));
#pragma unroll
        for (int k = 0; k < 7; k++) {
            int r = __reduce_add_sync(0xFFFFFFFFu, s[k]);
            if (lane == 0) sred[wid][k] = r;
        }
        __syncthreads();                           // A
        if (wid == 0) {
            // lane-parallel butterfly: all 7 counters at once (two value lanespaces)
            int va = sred[lane >> 2][lane & 3];
            int vb = ((lane & 3) < 3) ? sred[lane >> 2][4 + (lane & 3)] : 0;
            va += __shfl_xor_sync(0xFFFFFFFFu, va, 4);
            vb += __shfl_xor_sync(0xFFFFFFFFu, vb, 4);
            va += __shfl_xor_sync(0xFFFFFFFFu, va, 8);
            vb += __shfl_xor_sync(0xFFFFFFFFu, vb, 8);
            va += __shfl_xor_sync(0xFFFFFFFFu, va, 16);
            vb += __shfl_xor_sync(0xFFFFFFFFu, vb, 16);
            int c0 = __shfl_sync(0xFFFFFFFFu, va, 0);
            int c1 = __shfl_sync(0xFFFFFFFFu, va, 1);
            int c2 = __shfl_sync(0xFFFFFFFFu, va, 2);
            int c3 = __shfl_sync(0xFFFFFFFFu, va, 3);
            int c4 = __shfl_sync(0xFFFFFFFFu, vb, 0);
            int c5 = __shfl_sync(0xFFFFFFFFu, vb, 1);
            int c6 = __shfl_sync(0xFFFFFFFFu, vb, 2);
            if (lane == 0) {
                st_rel_i4(&g_st[0][blockIdx.x].v, make_int4(c0, c1, c2, (TAG << 20) | c3));
                st_rel_i4(&g_tt[blockIdx.x].v,    make_int4(c4, c5, c6, TAG << 20));
            }
        }
        if (tid < 128) {
            int4 pf, pt;
            const int4* sf = &g_st[0][abase + tid].v;
            const int4* st = &g_tt[abase + tid].v;
            do { pf = ld_acq_i4(sf); } while (((unsigned)pf.w >> 20) != TAG);
            do { pt = ld_acq_i4(st); } while (((unsigned)pt.w >> 20) != TAG);
            pf.w &= 0xFFFFF;
            int cc[7] = {pf.x, pf.y, pf.z, pf.w, pt.x, pt.y, pt.z};
#pragma unroll
            for (int k = 0; k < 7; k++) {
                int r = __reduce_add_sync(0xFFFFFFFFu, cc[k]);
                if (lane == 0) spp[wid][k] = r;
            }
        }
        __syncthreads();                           // B
        if (wid == 0) {
            int val = (lane < 28) ? spp[lane & 3][lane >> 2] : 0;
            val += __shfl_xor_sync(0xFFFFFFFFu, val, 1);
            val += __shfl_xor_sync(0xFFFFFFFFu, val, 2);
            // counter k total now at lane 4k
            int F3 = __shfl_sync(0xFFFFFFFFu, val, 12);
            float fc = __fadd_rn((float)F3, 1e-6f);
            float bc = __fadd_rn((float)(HW - F3), 1e-6f);
            int m  = lane % 3;
            int Fk = __shfl_sync(0xFFFFFFFFu, val, m * 4);
            int Tk = __shfl_sync(0xFFFFFFFFu, val, 16 + m * 4);
            if (lane < 3)                 smF[lane] = __fdiv_rn((float)Fk, fc);
            else if (lane < 6)            smB[m]    = __fdiv_rn((float)(Tk - Fk), bc);
            if (lane >= 6 && lane < 9)    sT[m]     = Tk;
        }
        __syncthreads();                           // C
    }

    // ---------- phase 3: 5 ICM iterations ----------
    for (int it = 0; it < NITER; ++it) {
        const unsigned* __restrict__ ga = g_alf[it];
        const float fm0 = smF[0], fm1 = smF[1], fm2 = smF[2];
        const float bm0 = smB[0], bm1 = smB[1], bm2 = smB[2];

        unsigned naw[WPT];
#pragma unroll
        for (int u = 0; u < WPT; u++) {
            const int L = lw[u];
            unsigned cen = aw[u];
            unsigned upw = (lrv[u] > 0) ? salpha[L - 128]
                         : ((yv[u] > 0) ? __ldcg(ga + idx4[u] - 128) : cen);
            unsigned dnw = (lrv[u] < 3) ? salpha[L + 128]
                         : ((yv[u] < Hn - 1) ? __ldcg(ga + idx4[u] + 128) : cen);
            unsigned lfb = (cv[u] > 0)   ? (salpha[L - 1] >> 24) : (cen & 255u);
            unsigned rtb = (cv[u] < 127) ? (salpha[L + 1] & 255u) : (cen >> 24);
            unsigned lfw = (cen << 8) | lfb;
            unsigned rtw = (cen >> 8) | (rtb << 24);
            unsigned nbw = __vadd4(__vadd4(upw, dnw), __vadd4(lfw, rtw));

            unsigned nav = 0;
#pragma unroll
            for (int j = 0; j < 4; j++) {
                float i0 = (float)((rw[u] >> (8 * j)) & 255u);
                float i1 = (float)((gw[u] >> (8 * j)) & 255u);
                float i2 = (float)((bw[u] >> (8 * j)) & 255u);
                float nb = __fmul_rn((float)((nbw >> (8 * j)) & 255u), 0.25f);

                float d0 = __fsub_rn(i0, fm0);
                float d1 = __fsub_rn(i1, fm1);
                float d2 = __fsub_rn(i2, fm2);
                float dfg = __fadd_rn(__fadd_rn(__fmul_rn(d0, d0), __fmul_rn(d1, d1)),
                                      __fmul_rn(d2, d2));
                float e0 = __fsub_rn(i0, bm0);
                float e1 = __fsub_rn(i1, bm1);
                float e2 = __fsub_rn(i2, bm2);
                float dbg = __fadd_rn(__fadd_rn(__fmul_rn(e0, e0), __fmul_rn(e1, e1)),
                                      __fmul_rn(e2, e2));
                float pw = __fmul_rn(50.0f, __fsub_rn(__fmul_rn(2.0f, nb), 1.0f));
                float score = __fadd_rn(__fsub_rn(dbg, dfg), pw);
                if (score > 0.0f) nav |= 1u << (8 * j);
            }
            naw[u] = (nav & ~fixm[u]) | fixv[u];
        }

        if (it == NITER - 1) {
#pragma unroll
            for (int u = 0; u < WPT; u++) {
                unsigned a = naw[u];
                ((float4*)out)[idx4[u]] = make_float4(
                    (float)(a & 255u), (float)((a >> 8) & 255u),
                    (float)((a >> 16) & 255u), (float)(a >> 24));
            }
        } else {
            int s[4];
            s[0] = (int)__dp4a(rw[1], naw[1], __dp4a(rw[0], naw[0], 0u));
            s[1] = (int)__dp4a(gw[1], naw[1], __dp4a(gw[0], naw[0], 0u));
            s[2] = (int)__dp4a(bw[1], naw[1], __dp4a(bw[0], naw[0], 0u));
            s[3] = (int)__dp4a(0x01010101u, naw[1], __dp4a(0x01010101u, naw[0], 0u));
#pragma unroll
            for (int k = 0; k < 4; k++) {
                int r = __reduce_add_sync(0xFFFFFFFFu, s[k]);
                if (lane == 0) sred[wid][k] = r;
            }
            __syncthreads();                       // A: all salpha reads of this iter done
#pragma unroll
            for (int u = 0; u < WPT; u++) {
                aw[u] = naw[u];
                salpha[lw[u]] = naw[u];
                if (lrv[u] == 0 || lrv[u] == 3)
                    __stcg(&g_alf[it + 1][idx4[u]], naw[u]);
            }
            if (wid == 0) {
                int val = sred[lane >> 2][lane & 3];
                val += __shfl_xor_sync(0xFFFFFFFFu, val, 4);
                val += __shfl_xor_sync(0xFFFFFFFFu, val, 8);
                val += __shfl_xor_sync(0xFFFFFFFFu, val, 16);
                int c0 = __shfl_sync(0xFFFFFFFFu, val, 0);
                int c1 = __shfl_sync(0xFFFFFFFFu, val, 1);
                int c2 = __shfl_sync(0xFFFFFFFFu, val, 2);
                int c3 = __shfl_sync(0xFFFFFFFFu, val, 3);
                if (lane == 0)
                    st_rel_i4(&g_st[it + 1][blockIdx.x].v,
                              make_int4(c0, c1, c2, (TAG << 20) | c3));
            }
            if (tid < 128) {
                int4 p;
                const int4* sp = &g_st[it + 1][abase + tid].v;
                do { p = ld_acq_i4(sp); } while (((unsigned)p.w >> 20) != TAG);
                p.w &= 0xFFFFF;
                int cc[4] = {p.x, p.y, p.z, p.w};
#pragma unroll
                for (int k = 0; k < 4; k++) {
                    int r = __reduce_add_sync(0xFFFFFFFFu, cc[k]);
                    if (lane == 0) spp[wid][k] = r;
                }
            }
            __syncthreads();                       // B
            if (wid == 0) {
                int val = (lane < 16) ? spp[lane & 3][lane >> 2] : 0;
                val += __shfl_xor_sync(0xFFFFFFFFu, val, 1);
                val += __shfl_xor_sync(0xFFFFFFFFu, val, 2);
                int F3 = __shfl_sync(0xFFFFFFFFu, val, 12);
                float fc = __fadd_rn((float)F3, 1e-6f);
                float bc = __fadd_rn((float)(HW - F3), 1e-6f);
                int m  = lane % 3;
                int Fk = __shfl_sync(0xFFFFFFFFu, val, m * 4);
                if (lane < 3)      smF[lane] = __fdiv_rn((float)Fk, fc);
                else if (lane < 6) smB[m]    = __fdiv_rn((float)(sT[m] - Fk), bc);
            }
            __syncthreads();                       // C
        }
    }
}

// ============================================================
extern "C" void kernel_launch(void* const* d_in, const int* in_sizes, int n_in,
                              void* d_out, int out_size) {
    const float* feat = (const float*)d_in[0];
    const int*   mask = (const int*)d_in[1];
    float*       out  = (float*)d_out;

    k_main<<<NB, NT>>>(feat, mask, out);
}